// round 2
// baseline (speedup 1.0000x reference)
#include <cuda_runtime.h>
#include <math.h>

#define NNODES 1024
#define FD 64
#define MAXB 4

// ---- scratch (no allocations allowed) ----
__device__ float    g_node[MAXB * NNODES * FD];          // scatter accumulator
__device__ float    g_Wh  [MAXB * NNODES * FD];          // Wh = normalize(node) @ W
__device__ float    g_f1  [MAXB * NNODES];
__device__ float    g_f2  [MAXB * NNODES];
__device__ unsigned g_adj [MAXB * NNODES * (NNODES/32)]; // adjacency bitmask

// ------------------------------------------------------------------
// K0: zero the accumulators
// ------------------------------------------------------------------
__global__ void k_zero(int nodeWords, int adjWords) {
    int i = blockIdx.x * blockDim.x + threadIdx.x;
    int stride = gridDim.x * blockDim.x;
    for (int t = i; t < nodeWords; t += stride) g_node[t] = 0.0f;
    for (int t = i; t < adjWords;  t += stride) g_adj[t]  = 0u;
}

// ------------------------------------------------------------------
// K1: scatter-add flow features at dst nodes + adjacency bitmask.
// One thread per (flow, 4-dim chunk): 16 threads per flow.
// ------------------------------------------------------------------
__global__ void k_scatter(const float4* __restrict__ ff,
                          const int* __restrict__ src,
                          const int* __restrict__ dst,
                          int B, int S) {
    int t = blockIdx.x * blockDim.x + threadIdx.x;
    int total = B * S * 16;
    if (t >= total) return;
    int flow = t >> 4;
    int c    = t & 15;
    int b    = flow / S;
    int d    = dst[flow];

    float4 v = ff[t];  // (flow*64 + c*4)/4 == flow*16 + c == t
    float* p = &g_node[(b * NNODES + d) * FD + c * 4];
    asm volatile("red.global.add.v4.f32 [%0], {%1,%2,%3,%4};"
                 :: "l"(p), "f"(v.x), "f"(v.y), "f"(v.z), "f"(v.w)
                 : "memory");

    if (c == 0) {
        int sI = src[flow];
        atomicOr(&g_adj[(b * NNODES + sI) * 32 + (d  >> 5)], 1u << (d  & 31));
        atomicOr(&g_adj[(b * NNODES + d ) * 32 + (sI >> 5)], 1u << (sI & 31));
    }
}

// ------------------------------------------------------------------
// K2: h = node / max(||node||,1e-12);  Wh = h @ W;  f1 = Wh·a1;  f2 = Wh·a2
// One warp per node; 8 warps per block; W cached in smem.
// ------------------------------------------------------------------
__global__ void k_nodeproc(const float* __restrict__ W,
                           const float* __restrict__ a1,
                           const float* __restrict__ a2,
                           int BN) {
    __shared__ float sW[FD * FD];
    __shared__ float sh[8][FD];
    int tid = threadIdx.x;
    for (int i = tid; i < FD * FD; i += 256) sW[i] = W[i];
    __syncthreads();

    int warp = tid >> 5, lane = tid & 31;
    int n = blockIdx.x * 8 + warp;
    if (n >= BN) return;

    float x0 = g_node[n * FD + lane];
    float x1 = g_node[n * FD + lane + 32];
    float ss = x0 * x0 + x1 * x1;
    #pragma unroll
    for (int o = 16; o; o >>= 1) ss += __shfl_xor_sync(~0u, ss, o);
    float norm = fmaxf(sqrtf(ss), 1e-12f);
    float inv  = 1.0f / norm;

    sh[warp][lane]      = x0 * inv;
    sh[warp][lane + 32] = x1 * inv;
    __syncwarp();

    float w0 = 0.0f, w1 = 0.0f;
    #pragma unroll
    for (int d = 0; d < FD; d++) {
        float hd = sh[warp][d];
        w0 = fmaf(hd, sW[d * FD + lane],      w0);
        w1 = fmaf(hd, sW[d * FD + lane + 32], w1);
    }
    g_Wh[n * FD + lane]      = w0;
    g_Wh[n * FD + lane + 32] = w1;

    float p1 = w0 * a1[lane] + w1 * a1[lane + 32];
    float p2 = w0 * a2[lane] + w1 * a2[lane + 32];
    #pragma unroll
    for (int o = 16; o; o >>= 1) {
        p1 += __shfl_xor_sync(~0u, p1, o);
        p2 += __shfl_xor_sync(~0u, p2, o);
    }
    if (lane == 0) { g_f1[n] = p1; g_f2[n] = p2; }
}

// ------------------------------------------------------------------
// K3: masked softmax attention + elu.  One warp per (b,i) row.
// Masked entries contribute exp(NEG_BIG - m) == 0 exactly in fp32,
// except when the whole row is masked -> uniform 1/N.
// ------------------------------------------------------------------
__global__ void k_attn(float* __restrict__ out, int BN) {
    int warp = threadIdx.x >> 5, lane = threadIdx.x & 31;
    int row = blockIdx.x * 4 + warp;
    if (row >= BN) return;
    int b = row >> 10;
    const float* f2 = &g_f2[b * NNODES];
    const float* Wh = &g_Wh[b * NNODES * FD];

    unsigned word = g_adj[row * 32 + lane];
    int cnt = __popc(word);
    #pragma unroll
    for (int o = 16; o; o >>= 1) cnt += __shfl_xor_sync(~0u, cnt, o);

    float f1i = g_f1[row];
    float o0 = 0.0f, o1 = 0.0f;

    if (cnt == 0) {
        // fully masked row: softmax of equal values -> uniform 1/N
        for (int j = 0; j < NNODES; j++) {
            o0 += Wh[j * FD + lane];
            o1 += Wh[j * FD + lane + 32];
        }
        o0 *= (1.0f / NNODES);
        o1 *= (1.0f / NNODES);
    } else {
        // pass 1: row max over active entries (lane handles j = w*32+lane)
        float m = -INFINITY;
        #pragma unroll
        for (int w = 0; w < 32; w++) {
            unsigned mw = __shfl_sync(~0u, word, w);
            if ((mw >> lane) & 1u) {
                float e = f1i + f2[w * 32 + lane];
                e = e >= 0.0f ? e : 0.2f * e;
                m = fmaxf(m, e);
            }
        }
        #pragma unroll
        for (int o = 16; o; o >>= 1) m = fmaxf(m, __shfl_xor_sync(~0u, m, o));

        // pass 2: warp-converged iteration over set bits; accumulate
        float s = 0.0f;
        #pragma unroll 1
        for (int w = 0; w < 32; w++) {
            unsigned mw = __shfl_sync(~0u, word, w);
            while (mw) {
                int bpos = __ffs(mw) - 1;
                mw &= mw - 1;
                int j = w * 32 + bpos;
                float e = f1i + f2[j];          // broadcast load
                e = e >= 0.0f ? e : 0.2f * e;
                float p = __expf(e - m);
                s += p;
                o0 = fmaf(p, Wh[j * FD + lane],      o0);
                o1 = fmaf(p, Wh[j * FD + lane + 32], o1);
            }
        }
        float invs = 1.0f / s;
        o0 *= invs;
        o1 *= invs;
    }

    // elu
    o0 = o0 > 0.0f ? o0 : expm1f(o0);
    o1 = o1 > 0.0f ? o1 : expm1f(o1);
    out[row * FD + lane]      = o0;
    out[row * FD + lane + 32] = o1;
}

// ------------------------------------------------------------------
extern "C" void kernel_launch(void* const* d_in, const int* in_sizes, int n_in,
                              void* d_out, int out_size) {
    const float* ff  = (const float*)d_in[0];
    const int*   src = (const int*)  d_in[1];
    const int*   dst = (const int*)  d_in[2];
    const float* W   = (const float*)d_in[9];
    const float* a1  = (const float*)d_in[10];
    const float* a2  = (const float*)d_in[11];

    int B = out_size / (NNODES * FD);       // 4
    int S = in_sizes[1] / B;                // 16384
    int BN = B * NNODES;

    int nodeWords = BN * FD;
    int adjWords  = BN * 32;
    k_zero<<<256, 256>>>(nodeWords, adjWords);

    int total = B * S * 16;
    k_scatter<<<(total + 255) / 256, 256>>>((const float4*)ff, src, dst, B, S);

    k_nodeproc<<<(BN + 7) / 8, 256>>>(W, a1, a2, BN);

    k_attn<<<(BN + 3) / 4, 128>>>((float*)d_out, BN);
}

// round 4
// speedup vs baseline: 1.7274x; 1.7274x over previous
#include <cuda_runtime.h>
#include <math.h>

#define NNODES 1024
#define FD 64
#define MAXB 4

// ---- scratch (no allocations allowed) ----
__device__ float    g_node[MAXB * NNODES * FD];          // scatter accumulator
__device__ float    g_Wh  [MAXB * NNODES * FD];          // Wh = normalize(node) @ W
__device__ float    g_f1  [MAXB * NNODES];
__device__ float    g_f2  [MAXB * NNODES];
__device__ unsigned g_adj [MAXB * NNODES * (NNODES/32)]; // adjacency bitmask

// ------------------------------------------------------------------
// K0: zero the accumulators
// ------------------------------------------------------------------
__global__ void k_zero(int nodeWords, int adjWords) {
    int i = blockIdx.x * blockDim.x + threadIdx.x;
    int stride = gridDim.x * blockDim.x;
    for (int t = i; t < nodeWords; t += stride) g_node[t] = 0.0f;
    for (int t = i; t < adjWords;  t += stride) g_adj[t]  = 0u;
}

// ------------------------------------------------------------------
// K1: scatter-add flow features at dst nodes + adjacency bitmask.
// One thread per (flow, 4-dim chunk): 16 threads per flow.
// ------------------------------------------------------------------
__global__ void k_scatter(const float4* __restrict__ ff,
                          const int* __restrict__ src,
                          const int* __restrict__ dst,
                          int B, int S) {
    int t = blockIdx.x * blockDim.x + threadIdx.x;
    int total = B * S * 16;
    if (t >= total) return;
    int flow = t >> 4;
    int c    = t & 15;
    int b    = flow / S;
    int d    = dst[flow];

    float4 v = ff[t];
    float* p = &g_node[(b * NNODES + d) * FD + c * 4];
    asm volatile("red.global.add.v4.f32 [%0], {%1,%2,%3,%4};"
                 :: "l"(p), "f"(v.x), "f"(v.y), "f"(v.z), "f"(v.w)
                 : "memory");

    if (c == 0) {
        int sI = src[flow];
        atomicOr(&g_adj[(b * NNODES + sI) * 32 + (d  >> 5)], 1u << (d  & 31));
        atomicOr(&g_adj[(b * NNODES + d ) * 32 + (sI >> 5)], 1u << (sI & 31));
    }
}

// ------------------------------------------------------------------
// K2: h = node / max(||node||,1e-12);  Wh = h @ W;  f1 = Wh·a1;  f2 = Wh·a2
// One warp per node; 8 warps per block; W cached in smem.
// ------------------------------------------------------------------
__global__ void k_nodeproc(const float* __restrict__ W,
                           const float* __restrict__ a1,
                           const float* __restrict__ a2,
                           int BN) {
    __shared__ float sW[FD * FD];
    __shared__ float sh[8][FD];
    int tid = threadIdx.x;
    for (int i = tid; i < FD * FD; i += 256) sW[i] = W[i];
    __syncthreads();

    int warp = tid >> 5, lane = tid & 31;
    int n = blockIdx.x * 8 + warp;
    if (n >= BN) return;

    float x0 = g_node[n * FD + lane];
    float x1 = g_node[n * FD + lane + 32];
    float ss = x0 * x0 + x1 * x1;
    #pragma unroll
    for (int o = 16; o; o >>= 1) ss += __shfl_xor_sync(~0u, ss, o);
    float norm = fmaxf(sqrtf(ss), 1e-12f);
    float inv  = 1.0f / norm;

    sh[warp][lane]      = x0 * inv;
    sh[warp][lane + 32] = x1 * inv;
    __syncwarp();

    float w0 = 0.0f, w1 = 0.0f;
    #pragma unroll
    for (int d = 0; d < FD; d++) {
        float hd = sh[warp][d];
        w0 = fmaf(hd, sW[d * FD + lane],      w0);
        w1 = fmaf(hd, sW[d * FD + lane + 32], w1);
    }
    g_Wh[n * FD + lane]      = w0;
    g_Wh[n * FD + lane + 32] = w1;

    float p1 = w0 * a1[lane] + w1 * a1[lane + 32];
    float p2 = w0 * a2[lane] + w1 * a2[lane + 32];
    #pragma unroll
    for (int o = 16; o; o >>= 1) {
        p1 += __shfl_xor_sync(~0u, p1, o);
        p2 += __shfl_xor_sync(~0u, p2, o);
    }
    if (lane == 0) { g_f1[n] = p1; g_f2[n] = p2; }
}

// ------------------------------------------------------------------
// K3 v2: masked softmax attention + elu.  One BLOCK (128 thr) per row.
//   1. warp0 compacts mask bits -> jlist in smem
//   2. thread-parallel e_j, block max, p_j = exp(e-m), block sum
//   3. 4 warps split the AXPY over jlist, reduce via smem
// ------------------------------------------------------------------
__global__ void k_attn(float* __restrict__ out) {
    __shared__ int   s_jl[NNODES];
    __shared__ float s_pv[NNODES];
    __shared__ float s_part[4][FD];
    __shared__ float s_red[4];
    __shared__ int   s_cnt;

    int row  = blockIdx.x;
    int b    = row >> 10;
    int tid  = threadIdx.x;
    int warp = tid >> 5, lane = tid & 31;

    const float* f2 = &g_f2[b * NNODES];
    const float* Wh = &g_Wh[b * NNODES * FD];

    // --- 1. compact active-j list (warp 0) ---
    if (warp == 0) {
        unsigned word = g_adj[row * 32 + lane];
        int pc = __popc(word);
        // inclusive scan -> exclusive offset
        int scan = pc;
        #pragma unroll
        for (int o = 1; o < 32; o <<= 1) {
            int v = __shfl_up_sync(~0u, scan, o);
            if (lane >= o) scan += v;
        }
        int excl = scan - pc;
        if (lane == 31) s_cnt = scan;
        int base = lane * 32;
        while (word) {
            int bp = __ffs(word) - 1;
            word &= word - 1;
            s_jl[excl++] = base + bp;
        }
    }
    __syncthreads();
    int cnt = s_cnt;

    float o0 = 0.0f, o1 = 0.0f;
    float scale;

    if (cnt == 0) {
        // fully masked row: uniform softmax -> mean of Wh rows
        for (int j = warp; j < NNODES; j += 4) {
            o0 += Wh[j * FD + lane];
            o1 += Wh[j * FD + lane + 32];
        }
        scale = 1.0f / NNODES;
    } else {
        float f1i = g_f1[row];
        // --- 2a. e_j + block max ---
        float mymax = -INFINITY;
        for (int i = tid; i < cnt; i += 128) {
            int j = s_jl[i];
            float e = f1i + f2[j];
            e = e >= 0.0f ? e : 0.2f * e;
            s_pv[i] = e;
            mymax = fmaxf(mymax, e);
        }
        #pragma unroll
        for (int o = 16; o; o >>= 1) mymax = fmaxf(mymax, __shfl_xor_sync(~0u, mymax, o));
        if (lane == 0) s_red[warp] = mymax;
        __syncthreads();
        float m = fmaxf(fmaxf(s_red[0], s_red[1]), fmaxf(s_red[2], s_red[3]));

        // --- 2b. p_j + block sum ---
        float mysum = 0.0f;
        for (int i = tid; i < cnt; i += 128) {
            float p = __expf(s_pv[i] - m);
            s_pv[i] = p;
            mysum += p;
        }
        #pragma unroll
        for (int o = 16; o; o >>= 1) mysum += __shfl_xor_sync(~0u, mysum, o);
        __syncthreads();                       // s_red reuse
        if (lane == 0) s_red[warp] = mysum;
        __syncthreads();
        float s = s_red[0] + s_red[1] + s_red[2] + s_red[3];

        // --- 3. AXPY split across 4 warps ---
        for (int i = warp; i < cnt; i += 4) {
            int j   = s_jl[i];
            float p = s_pv[i];
            o0 = fmaf(p, Wh[j * FD + lane],      o0);
            o1 = fmaf(p, Wh[j * FD + lane + 32], o1);
        }
        scale = 1.0f / s;
    }

    s_part[warp][lane]      = o0;
    s_part[warp][lane + 32] = o1;
    __syncthreads();
    if (warp == 0) {
        o0 = s_part[0][lane]      + s_part[1][lane]      + s_part[2][lane]      + s_part[3][lane];
        o1 = s_part[0][lane + 32] + s_part[1][lane + 32] + s_part[2][lane + 32] + s_part[3][lane + 32];
        o0 *= scale;
        o1 *= scale;
        o0 = o0 > 0.0f ? o0 : expm1f(o0);
        o1 = o1 > 0.0f ? o1 : expm1f(o1);
        out[row * FD + lane]      = o0;
        out[row * FD + lane + 32] = o1;
    }
}

// ------------------------------------------------------------------
extern "C" void kernel_launch(void* const* d_in, const int* in_sizes, int n_in,
                              void* d_out, int out_size) {
    const float* ff  = (const float*)d_in[0];
    const int*   src = (const int*)  d_in[1];
    const int*   dst = (const int*)  d_in[2];
    const float* W   = (const float*)d_in[9];
    const float* a1  = (const float*)d_in[10];
    const float* a2  = (const float*)d_in[11];

    int B = out_size / (NNODES * FD);       // 4
    int S = in_sizes[1] / B;                // 16384
    int BN = B * NNODES;

    int nodeWords = BN * FD;
    int adjWords  = BN * 32;
    k_zero<<<256, 256>>>(nodeWords, adjWords);

    int total = B * S * 16;
    k_scatter<<<(total + 255) / 256, 256>>>((const float4*)ff, src, dst, B, S);

    k_nodeproc<<<(BN + 7) / 8, 256>>>(W, a1, a2, BN);

    k_attn<<<BN, 128>>>((float*)d_out);
}